// round 2
// baseline (speedup 1.0000x reference)
#include <cuda_runtime.h>

#define BATCH 128
#define DIM   4096

typedef unsigned long long ull;

// ---- packed f32x2 helpers (Blackwell) ----
__device__ __forceinline__ ull pack2(float lo, float hi) {
    ull r;
    asm("mov.b64 %0, {%1, %2};" : "=l"(r) : "f"(lo), "f"(hi));
    return r;
}
__device__ __forceinline__ void unpack2(ull v, float& lo, float& hi) {
    asm("mov.b64 {%0, %1}, %2;" : "=f"(lo), "=f"(hi) : "l"(v));
}
__device__ __forceinline__ ull ffma2(ull a, ull b, ull c) {
    ull d;
    asm("fma.rn.f32x2 %0, %1, %2, %3;" : "=l"(d) : "l"(a), "l"(b), "l"(c));
    return d;
}

// logical->physical smem index: i + (i>>4)  (pad one float2 per 16)
__device__ __forceinline__ int phys(int i) { return i + (i >> 4); }

// One 16x16 complex matvec step over 256 fibers.
// PS = physical stride between consecutive fiber elements.
// Thread (f,q): fiber f, computes outputs k = q, q+4, q+8, q+12.
// Gate layout: G[kp*16 + k] = float4(Ur, Ur, -Ui, Ui) of U[k][kp].
template<int PS>
__device__ __forceinline__ void do_step(const float2* __restrict__ IN,
                                        float2* __restrict__ OUT,
                                        const float4* __restrict__ G,
                                        int pb, int q)
{
    ull acc0 = 0ULL, acc1 = 0ULL, acc2 = 0ULL, acc3 = 0ULL;
    #pragma unroll
    for (int kp = 0; kp < 16; kp++) {
        float2 x = IN[pb + kp * PS];
        ull xp = pack2(x.x, x.y);    // (xr, xi)
        ull xs = pack2(x.y, x.x);    // (xi, xr)
        const float4* Gr = G + kp * 16 + q;
        ulonglong2 u0 = *reinterpret_cast<const ulonglong2*>(Gr + 0);
        ulonglong2 u1 = *reinterpret_cast<const ulonglong2*>(Gr + 4);
        ulonglong2 u2 = *reinterpret_cast<const ulonglong2*>(Gr + 8);
        ulonglong2 u3 = *reinterpret_cast<const ulonglong2*>(Gr + 12);
        acc0 = ffma2(u0.x, xp, acc0); acc0 = ffma2(u0.y, xs, acc0);
        acc1 = ffma2(u1.x, xp, acc1); acc1 = ffma2(u1.y, xs, acc1);
        acc2 = ffma2(u2.x, xp, acc2); acc2 = ffma2(u2.y, xs, acc2);
        acc3 = ffma2(u3.x, xp, acc3); acc3 = ffma2(u3.y, xs, acc3);
    }
    float lo, hi;
    unpack2(acc0, lo, hi); OUT[pb + (q +  0) * PS] = make_float2(lo, hi);
    unpack2(acc1, lo, hi); OUT[pb + (q +  4) * PS] = make_float2(lo, hi);
    unpack2(acc2, lo, hi); OUT[pb + (q +  8) * PS] = make_float2(lo, hi);
    unpack2(acc3, lo, hi); OUT[pb + (q + 12) * PS] = make_float2(lo, hi);
}

__global__ __launch_bounds__(1024, 1)
void ulayer_kernel(const float* __restrict__ thetas,
                   const float* __restrict__ evecs,
                   const float* __restrict__ evals,
                   const float* __restrict__ sreal,
                   const float* __restrict__ simag,
                   float* __restrict__ out)
{
    extern __shared__ float2 smem[];
    float2* A  = smem;                                   // 4352 float2
    float2* Bv = smem + 4352;                            // 4352 float2
    float4* g4 = reinterpret_cast<float4*>(smem + 8704); // 3*256 float4

    const int t = threadIdx.x;
    const int b = blockIdx.x;

    // scratch overlay inside B (unused until step 0 writes it, after syncs)
    float* Vs = reinterpret_cast<float*>(Bv);   // 16 rows, stride 17
    float* cs = reinterpret_cast<float*>(Bv) + 288;
    float* sn = reinterpret_cast<float*>(Bv) + 336;

    // ---- stage V and sincos ----
    if (t < 256) {
        int j = t >> 4, m = t & 15;
        Vs[j * 17 + m] = evecs[t];
    }
    if (t >= 512 && t < 560) {
        int u = t - 512;
        int g = u >> 4, m = u & 15;
        float ang = thetas[g] * evals[m];
        float s, c;
        sincosf(ang, &s, &c);
        cs[g * 16 + m] = c;
        sn[g * 16 + m] = s;
    }
    __syncthreads();

    // ---- build gates (768 threads), transposed layout G[kp][k] ----
    if (t < 768) {
        int g = t >> 8, k = (t >> 4) & 15, kp = t & 15;
        float ar = 0.f, ai = 0.f;
        #pragma unroll
        for (int m = 0; m < 16; m++) {
            float p = Vs[k * 17 + m] * Vs[kp * 17 + m];
            ar += p * cs[g * 16 + m];
            ai += p * sn[g * 16 + m];
        }
        // U = Ur + i*Ui with Ur=ar, Ui=-ai; pack (Ur, Ur, -Ui, Ui)
        g4[g * 256 + kp * 16 + k] = make_float4(ar, ar, ai, -ai);
    }

    // ---- load state into A (concurrent with gate build) ----
    const float* srg = sreal + b * DIM;
    const float* sig = simag + b * DIM;
    #pragma unroll
    for (int w = 0; w < 4; w++) {
        int i = t + w * 1024;
        A[phys(i)] = make_float2(srg[i], sig[i]);
    }
    __syncthreads();

    // ---- three contractions, ping-pong A->B->A->B ----
    const int f = t >> 2, q = t & 3;

    // step 0: U2 on index c (stride 1), fibers base = f*16, phys base = f*17
    do_step<1>(A, Bv, g4 + 2 * 256, f * 17, q);
    __syncthreads();

    // step 1: U1 on index b (stride 16), base = (f>>4)*256 + (f&15)
    do_step<17>(Bv, A, g4 + 1 * 256, (f >> 4) * 272 + (f & 15), q);
    __syncthreads();

    // step 2: U0 on index a (stride 256), base = f
    do_step<272>(A, Bv, g4 + 0 * 256, f + (f >> 4), q);
    __syncthreads();

    // ---- write output [2, BATCH, DIM] from B ----
    float* outr = out + b * DIM;
    float* outi = out + (size_t)BATCH * DIM + b * DIM;
    #pragma unroll
    for (int w = 0; w < 4; w++) {
        int i = t + w * 1024;
        float2 v = Bv[phys(i)];
        outr[i] = v.x;
        outi[i] = v.y;
    }
}

extern "C" void kernel_launch(void* const* d_in, const int* in_sizes, int n_in,
                              void* d_out, int out_size) {
    const float* thetas = (const float*)d_in[0];
    const float* evecs  = (const float*)d_in[1];
    const float* evals  = (const float*)d_in[2];
    const float* sreal  = (const float*)d_in[3];
    const float* simag  = (const float*)d_in[4];

    const int smem_bytes = 8704 * sizeof(float2) + 3 * 256 * sizeof(float4); // 81920
    static bool attr_set = false;
    if (!attr_set) {
        cudaFuncSetAttribute(ulayer_kernel,
                             cudaFuncAttributeMaxDynamicSharedMemorySize,
                             smem_bytes);
        attr_set = true;
    }
    ulayer_kernel<<<BATCH, 1024, smem_bytes>>>(thetas, evecs, evals,
                                               sreal, simag, (float*)d_out);
}

// round 3
// speedup vs baseline: 1.4170x; 1.4170x over previous
#include <cuda_runtime.h>

#define BATCH 128
#define DIM   4096

typedef unsigned long long ull;

// ---- packed f32x2 helpers (Blackwell) ----
__device__ __forceinline__ ull pack2(float lo, float hi) {
    ull r;
    asm("mov.b64 %0, {%1, %2};" : "=l"(r) : "f"(lo), "f"(hi));
    return r;
}
__device__ __forceinline__ void unpack2(ull v, float& lo, float& hi) {
    asm("mov.b64 {%0, %1}, %2;" : "=f"(lo), "=f"(hi) : "l"(v));
}
__device__ __forceinline__ ull ffma2(ull a, ull b, ull c) {
    ull d;
    asm("fma.rn.f32x2 %0, %1, %2, %3;" : "=l"(d) : "l"(a), "l"(b), "l"(c));
    return d;
}

// logical->physical smem index: i + (i>>4) (pad one float2 per 16)
__device__ __forceinline__ int phys(int i) { return i + (i >> 4); }

// One 16x16 complex matvec over 256 fibers; 2 threads per fiber.
// Thread (f, q): owns fiber f, computes outputs k = 2j + q, j = 0..7.
// Gate layout: G[kp*16 + k] = float4(Ur, Ur, -Ui, Ui) of U[k][kp].
// The two partner lanes (q=0/1) load adjacent float4s -> 32B contiguous,
// conflict-free LDS.128.
template<int PS>
__device__ __forceinline__ void do_step(const float2* __restrict__ IN,
                                        float2* __restrict__ OUT,
                                        const float4* __restrict__ G,
                                        int pb, int q)
{
    ull acc[8];
    #pragma unroll
    for (int j = 0; j < 8; j++) acc[j] = 0ULL;

    #pragma unroll
    for (int kp = 0; kp < 16; kp++) {
        float2 x = IN[pb + kp * PS];
        ull xp = pack2(x.x, x.y);    // (xr, xi)
        ull xs = pack2(x.y, x.x);    // (xi, xr)
        const float4* Gr = G + kp * 16 + q;
        #pragma unroll
        for (int j = 0; j < 8; j++) {
            ulonglong2 u = *reinterpret_cast<const ulonglong2*>(Gr + 2 * j);
            acc[j] = ffma2(u.x, xp, acc[j]);   // += (Ur*xr, Ur*xi)
            acc[j] = ffma2(u.y, xs, acc[j]);   // += (-Ui*xi, Ui*xr)
        }
    }
    #pragma unroll
    for (int j = 0; j < 8; j++) {
        float lo, hi;
        unpack2(acc[j], lo, hi);
        OUT[pb + (2 * j + q) * PS] = make_float2(lo, hi);
    }
}

__global__ __launch_bounds__(512, 1)
void ulayer_kernel(const float* __restrict__ thetas,
                   const float* __restrict__ evecs,
                   const float* __restrict__ evals,
                   const float* __restrict__ sreal,
                   const float* __restrict__ simag,
                   float* __restrict__ out)
{
    extern __shared__ float2 smem[];
    float2* A  = smem;                                   // 4352 float2
    float2* Bv = smem + 4352;                            // 4352 float2
    float4* g4 = reinterpret_cast<float4*>(smem + 8704); // 3*256 float4

    const int t = threadIdx.x;
    const int b = blockIdx.x;

    // scratch overlay inside B (dead until step 0 writes B, after syncs)
    float* Vs = reinterpret_cast<float*>(Bv);   // 16 rows, stride 17
    float* cs = reinterpret_cast<float*>(Bv) + 288;
    float* sn = reinterpret_cast<float*>(Bv) + 336;

    // ---- stage V and sincos ----
    if (t < 256) {
        int j = t >> 4, m = t & 15;
        Vs[j * 17 + m] = evecs[t];               // V[j][m]
    }
    if (t >= 256 && t < 304) {
        int u = t - 256;
        int g = u >> 4, m = u & 15;
        float ang = thetas[g] * evals[m];
        float s, c;
        sincosf(ang, &s, &c);
        cs[g * 16 + m] = c;
        sn[g * 16 + m] = s;
    }
    __syncthreads();

    // ---- build gates, transposed layout G[kp][k] ----
    if (t < 256) {
        int k = t >> 4, kp = t & 15;
        #pragma unroll
        for (int g = 0; g < 3; g++) {
            float ar = 0.f, ai = 0.f;
            #pragma unroll
            for (int m = 0; m < 16; m++) {
                float p = Vs[k * 17 + m] * Vs[kp * 17 + m];
                ar += p * cs[g * 16 + m];
                ai += p * sn[g * 16 + m];
            }
            // U = ar - i*ai ; pack (Ur, Ur, -Ui, Ui) = (ar, ar, ai, -ai)
            g4[g * 256 + kp * 16 + k] = make_float4(ar, ar, ai, -ai);
        }
    }

    // ---- load state into A (concurrent with gate build) ----
    const float* srg = sreal + b * DIM;
    const float* sig = simag + b * DIM;
    #pragma unroll
    for (int w = 0; w < 8; w++) {
        int i = t + w * 512;
        A[phys(i)] = make_float2(srg[i], sig[i]);
    }
    __syncthreads();

    // ---- three contractions, ping-pong A->B->A->B ----
    const int f = t >> 1, q = t & 1;

    // step 0: U2 on index c (logical stride 1)
    do_step<1>(A, Bv, g4 + 2 * 256, f * 17, q);
    __syncthreads();

    // step 1: U1 on index b16 (logical stride 16)
    do_step<17>(Bv, A, g4 + 1 * 256, (f >> 4) * 272 + (f & 15), q);
    __syncthreads();

    // step 2: U0 on index a (logical stride 256)
    do_step<272>(A, Bv, g4 + 0 * 256, f + (f >> 4), q);
    __syncthreads();

    // ---- write output [2, BATCH, DIM] from B ----
    float* outr = out + b * DIM;
    float* outi = out + (size_t)BATCH * DIM + b * DIM;
    #pragma unroll
    for (int w = 0; w < 8; w++) {
        int i = t + w * 512;
        float2 v = Bv[phys(i)];
        outr[i] = v.x;
        outi[i] = v.y;
    }
}

extern "C" void kernel_launch(void* const* d_in, const int* in_sizes, int n_in,
                              void* d_out, int out_size) {
    const float* thetas = (const float*)d_in[0];
    const float* evecs  = (const float*)d_in[1];
    const float* evals  = (const float*)d_in[2];
    const float* sreal  = (const float*)d_in[3];
    const float* simag  = (const float*)d_in[4];

    const int smem_bytes = 8704 * sizeof(float2) + 3 * 256 * sizeof(float4); // 81920
    static bool attr_set = false;
    if (!attr_set) {
        cudaFuncSetAttribute(ulayer_kernel,
                             cudaFuncAttributeMaxDynamicSharedMemorySize,
                             smem_bytes);
        attr_set = true;
    }
    ulayer_kernel<<<BATCH, 512, smem_bytes>>>(thetas, evecs, evals,
                                              sreal, simag, (float*)d_out);
}

// round 4
// speedup vs baseline: 1.4800x; 1.0444x over previous
#include <cuda_runtime.h>

#define BATCH 128
#define DIM   4096

typedef unsigned long long ull;

// ---- packed f32x2 helpers (Blackwell) ----
__device__ __forceinline__ ull pack2(float lo, float hi) {
    ull r;
    asm("mov.b64 %0, {%1, %2};" : "=l"(r) : "f"(lo), "f"(hi));
    return r;
}
__device__ __forceinline__ void unpack2(ull v, float& lo, float& hi) {
    asm("mov.b64 {%0, %1}, %2;" : "=f"(lo), "=f"(hi) : "l"(v));
}
__device__ __forceinline__ ull ffma2(ull a, ull b, ull c) {
    ull d;
    asm("fma.rn.f32x2 %0, %1, %2, %3;" : "=l"(d) : "l"(a), "l"(b), "l"(c));
    return d;
}

// padded smem layout: keeps float4 accesses 16B-aligned and spreads
// stride-16 / stride-256 accesses across banks
__device__ __forceinline__ int phys(int i) {
    return i + 2 * (i >> 4) + 2 * (i >> 8);
}
#define BUF_F2 4640   // phys(4095)+1 rounded up

// ---- step 0: gate on the stride-1 index ----
// Thread (h, q): fibers fA=2h, fB=2h+1 (not adjacent in smem; elements within
// a fiber ARE contiguous -> float4 loads cover kp, kp+1 of one fiber).
// Gate layout: G[kp*16 + k] = float4(Ur, Ur, -Ui, Ui) of U[k][kp].
__device__ __forceinline__ void do_step0(const float2* __restrict__ IN,
                                         float2* __restrict__ OUT,
                                         const float4* __restrict__ G,
                                         int h, int q)
{
    const int pbA = 18 * (2 * h) + 2 * ((2 * h) >> 4);
    const int pbB = pbA + 18;

    ull accA[4], accB[4];
    #pragma unroll
    for (int j = 0; j < 4; j++) { accA[j] = 0ULL; accB[j] = 0ULL; }

    #pragma unroll
    for (int kp2 = 0; kp2 < 8; kp2++) {
        float4 a = *reinterpret_cast<const float4*>(IN + pbA + 2 * kp2);
        float4 bv = *reinterpret_cast<const float4*>(IN + pbB + 2 * kp2);
        // kp = 2*kp2
        {
            ull xpA = pack2(a.x, a.y),  xsA = pack2(a.y, a.x);
            ull xpB = pack2(bv.x, bv.y), xsB = pack2(bv.y, bv.x);
            const float4* Gr = G + (2 * kp2) * 16 + q;
            #pragma unroll
            for (int j = 0; j < 4; j++) {
                ulonglong2 u = *reinterpret_cast<const ulonglong2*>(Gr + 4 * j);
                accA[j] = ffma2(u.x, xpA, accA[j]);
                accA[j] = ffma2(u.y, xsA, accA[j]);
                accB[j] = ffma2(u.x, xpB, accB[j]);
                accB[j] = ffma2(u.y, xsB, accB[j]);
            }
        }
        // kp = 2*kp2 + 1
        {
            ull xpA = pack2(a.z, a.w),  xsA = pack2(a.w, a.z);
            ull xpB = pack2(bv.z, bv.w), xsB = pack2(bv.w, bv.z);
            const float4* Gr = G + (2 * kp2 + 1) * 16 + q;
            #pragma unroll
            for (int j = 0; j < 4; j++) {
                ulonglong2 u = *reinterpret_cast<const ulonglong2*>(Gr + 4 * j);
                accA[j] = ffma2(u.x, xpA, accA[j]);
                accA[j] = ffma2(u.y, xsA, accA[j]);
                accB[j] = ffma2(u.x, xpB, accB[j]);
                accB[j] = ffma2(u.y, xsB, accB[j]);
            }
        }
    }
    #pragma unroll
    for (int j = 0; j < 4; j++) {
        float lo, hi;
        int k = q + 4 * j;
        unpack2(accA[j], lo, hi); OUT[pbA + k] = make_float2(lo, hi);
        unpack2(accB[j], lo, hi); OUT[pbB + k] = make_float2(lo, hi);
    }
}

// ---- steps 1 & 2: fibers f=2h and f+1 are ADJACENT in smem (phys +1),
// so one float4 load fetches element kp of both fibers.
template<int PS>
__device__ __forceinline__ void do_step12(const float2* __restrict__ IN,
                                          float2* __restrict__ OUT,
                                          const float4* __restrict__ G,
                                          int pb, int q)
{
    ull accA[4], accB[4];
    #pragma unroll
    for (int j = 0; j < 4; j++) { accA[j] = 0ULL; accB[j] = 0ULL; }

    #pragma unroll
    for (int kp = 0; kp < 16; kp++) {
        float4 v = *reinterpret_cast<const float4*>(IN + pb + kp * PS);
        ull xpA = pack2(v.x, v.y), xsA = pack2(v.y, v.x);
        ull xpB = pack2(v.z, v.w), xsB = pack2(v.w, v.z);
        const float4* Gr = G + kp * 16 + q;
        #pragma unroll
        for (int j = 0; j < 4; j++) {
            ulonglong2 u = *reinterpret_cast<const ulonglong2*>(Gr + 4 * j);
            accA[j] = ffma2(u.x, xpA, accA[j]);
            accA[j] = ffma2(u.y, xsA, accA[j]);
            accB[j] = ffma2(u.x, xpB, accB[j]);
            accB[j] = ffma2(u.y, xsB, accB[j]);
        }
    }
    #pragma unroll
    for (int j = 0; j < 4; j++) {
        float lo, hi;
        int k = q + 4 * j;
        unpack2(accA[j], lo, hi); OUT[pb + k * PS]     = make_float2(lo, hi);
        unpack2(accB[j], lo, hi); OUT[pb + 1 + k * PS] = make_float2(lo, hi);
    }
}

__global__ __launch_bounds__(512, 1)
void ulayer_kernel(const float* __restrict__ thetas,
                   const float* __restrict__ evecs,
                   const float* __restrict__ evals,
                   const float* __restrict__ sreal,
                   const float* __restrict__ simag,
                   float* __restrict__ out)
{
    extern __shared__ float2 smem[];
    float2* A  = smem;                  // BUF_F2 float2
    float2* Bv = smem + BUF_F2;         // BUF_F2 float2
    float4* g4 = reinterpret_cast<float4*>(smem + 2 * BUF_F2); // 3*256 float4

    const int t = threadIdx.x;
    const int b = blockIdx.x;

    // scratch overlay inside B (dead until step 0 writes B, after syncs)
    float* Vs = reinterpret_cast<float*>(Bv);   // 16 rows, stride 17
    float* cs = reinterpret_cast<float*>(Bv) + 288;
    float* sn = reinterpret_cast<float*>(Bv) + 336;

    // ---- stage V and sincos ----
    if (t < 256) {
        int j = t >> 4, m = t & 15;
        Vs[j * 17 + m] = evecs[t];               // V[j][m]
    }
    if (t >= 256 && t < 304) {
        int u = t - 256;
        int g = u >> 4, m = u & 15;
        float ang = thetas[g] * evals[m];
        float s, c;
        sincosf(ang, &s, &c);
        cs[g * 16 + m] = c;
        sn[g * 16 + m] = s;
    }
    __syncthreads();

    // ---- build gates, transposed layout G[kp][k] ----
    if (t < 256) {
        int k = t >> 4, kp = t & 15;
        #pragma unroll
        for (int g = 0; g < 3; g++) {
            float ar = 0.f, ai = 0.f;
            #pragma unroll
            for (int m = 0; m < 16; m++) {
                float p = Vs[k * 17 + m] * Vs[kp * 17 + m];
                ar += p * cs[g * 16 + m];
                ai += p * sn[g * 16 + m];
            }
            // U = ar - i*ai ; pack (Ur, Ur, -Ui, Ui) = (ar, ar, ai, -ai)
            g4[g * 256 + kp * 16 + k] = make_float4(ar, ar, ai, -ai);
        }
    }

    // ---- load state into A (concurrent with gate build) ----
    const float* srg = sreal + b * DIM;
    const float* sig = simag + b * DIM;
    #pragma unroll
    for (int w = 0; w < 8; w++) {
        int i = t + w * 512;
        A[phys(i)] = make_float2(srg[i], sig[i]);
    }
    __syncthreads();

    const int h = t >> 2, q = t & 3;   // h in [0,128), q in [0,4)

    // step 0: U2 on stride-1 index
    do_step0(A, Bv, g4 + 2 * 256, h, q);
    __syncthreads();

    // step 1: U1 on stride-16 index; fiber pair f=2h, 2h+1
    {
        int f = 2 * h;
        int pb = (f >> 4) * 290 + (f & 15);
        do_step12<18>(Bv, A, g4 + 1 * 256, pb, q);
    }
    __syncthreads();

    // step 2: U0 on stride-256 index
    {
        int f = 2 * h;
        int pb = f + 2 * (f >> 4);
        do_step12<290>(A, Bv, g4 + 0 * 256, pb, q);
    }
    __syncthreads();

    // ---- write output [2, BATCH, DIM] from B ----
    float* outr = out + b * DIM;
    float* outi = out + (size_t)BATCH * DIM + b * DIM;
    #pragma unroll
    for (int w = 0; w < 8; w++) {
        int i = t + w * 512;
        float2 v = Bv[phys(i)];
        outr[i] = v.x;
        outi[i] = v.y;
    }
}

extern "C" void kernel_launch(void* const* d_in, const int* in_sizes, int n_in,
                              void* d_out, int out_size) {
    const float* thetas = (const float*)d_in[0];
    const float* evecs  = (const float*)d_in[1];
    const float* evals  = (const float*)d_in[2];
    const float* sreal  = (const float*)d_in[3];
    const float* simag  = (const float*)d_in[4];

    const int smem_bytes = 2 * BUF_F2 * sizeof(float2) + 3 * 256 * sizeof(float4);
    static bool attr_set = false;
    if (!attr_set) {
        cudaFuncSetAttribute(ulayer_kernel,
                             cudaFuncAttributeMaxDynamicSharedMemorySize,
                             smem_bytes);
        attr_set = true;
    }
    ulayer_kernel<<<BATCH, 512, smem_bytes>>>(thetas, evecs, evals,
                                              sreal, simag, (float*)d_out);
}

// round 5
// speedup vs baseline: 1.6364x; 1.1057x over previous
#include <cuda_runtime.h>

#define BATCH 128
#define DIM   4096

typedef unsigned long long ull;

__device__ __forceinline__ void unpack2(ull v, float& lo, float& hi) {
    asm("mov.b64 {%0, %1}, %2;" : "=f"(lo), "=f"(hi) : "l"(v));
}
__device__ __forceinline__ ull ffma2(ull a, ull b, ull c) {
    ull d;
    asm("fma.rn.f32x2 %0, %1, %2, %3;" : "=l"(d) : "l"(a), "l"(b), "l"(c));
    return d;
}

// padded smem layout: float4-aligned, spreads strided fibers across banks
__device__ __forceinline__ int phys(int i) {
    return i + 2 * (i >> 4) + 2 * (i >> 8);
}
#define BUF_F2 4640

// Complex accumulation without operand swap:
//   accA += (Ur,Ur)*(xr,xi)   -> (sum Ur*xr, sum Ur*xi)
//   accB += (Ui,Ui)*(xr,xi)   -> (sum Ui*xr, sum Ui*xi)
//   yr = accA.lo - accB.hi ;  yi = accA.hi + accB.lo
// Gate entry g4 = float4(Ur, Ur, Ui, Ui) loaded as ulonglong2.

// ---- step 0: contracted index has logical stride 1 ----
// Thread (h, q): fibers 4h..4h+3 (fiber stride 18 in phys), outputs k = q+4j.
__device__ __forceinline__ void do_step0(const float2* __restrict__ IN,
                                         float2* __restrict__ OUT,
                                         const float4* __restrict__ G,
                                         int h, int q)
{
    const int pb0 = 72 * h + 2 * (h >> 2);

    ull accA[4][4], accB[4][4];
    #pragma unroll
    for (int f = 0; f < 4; f++)
        #pragma unroll
        for (int j = 0; j < 4; j++) { accA[f][j] = 0ULL; accB[f][j] = 0ULL; }

    #pragma unroll
    for (int kp2 = 0; kp2 < 8; kp2++) {
        // per fiber: one float4 = elements kp=2*kp2, 2*kp2+1
        float4 xv[4];
        #pragma unroll
        for (int f = 0; f < 4; f++)
            xv[f] = *reinterpret_cast<const float4*>(IN + pb0 + 18 * f + 2 * kp2);

        #pragma unroll
        for (int half = 0; half < 2; half++) {
            const float4* Gr = G + (2 * kp2 + half) * 16 + q;
            ulonglong2 g0 = *reinterpret_cast<const ulonglong2*>(Gr + 0);
            ulonglong2 g1 = *reinterpret_cast<const ulonglong2*>(Gr + 4);
            ulonglong2 g2 = *reinterpret_cast<const ulonglong2*>(Gr + 8);
            ulonglong2 g3 = *reinterpret_cast<const ulonglong2*>(Gr + 12);
            #pragma unroll
            for (int f = 0; f < 4; f++) {
                ull xp = half ? *(reinterpret_cast<ull*>(&xv[f]) + 1)
                              : *reinterpret_cast<ull*>(&xv[f]);
                accA[f][0] = ffma2(g0.x, xp, accA[f][0]);
                accB[f][0] = ffma2(g0.y, xp, accB[f][0]);
                accA[f][1] = ffma2(g1.x, xp, accA[f][1]);
                accB[f][1] = ffma2(g1.y, xp, accB[f][1]);
                accA[f][2] = ffma2(g2.x, xp, accA[f][2]);
                accB[f][2] = ffma2(g2.y, xp, accB[f][2]);
                accA[f][3] = ffma2(g3.x, xp, accA[f][3]);
                accB[f][3] = ffma2(g3.y, xp, accB[f][3]);
            }
        }
    }
    #pragma unroll
    for (int f = 0; f < 4; f++)
        #pragma unroll
        for (int j = 0; j < 4; j++) {
            float alo, ahi, blo, bhi;
            unpack2(accA[f][j], alo, ahi);
            unpack2(accB[f][j], blo, bhi);
            OUT[pb0 + 18 * f + (q + 4 * j)] = make_float2(alo - bhi, ahi + blo);
        }
}

// ---- steps 1 & 2: 4 fibers adjacent in phys (+1); PS = phys stride along kp
template<int PS>
__device__ __forceinline__ void do_step12(const float2* __restrict__ IN,
                                          float2* __restrict__ OUT,
                                          const float4* __restrict__ G,
                                          int pb, int q)
{
    ull accA[4][4], accB[4][4];
    #pragma unroll
    for (int f = 0; f < 4; f++)
        #pragma unroll
        for (int j = 0; j < 4; j++) { accA[f][j] = 0ULL; accB[f][j] = 0ULL; }

    #pragma unroll
    for (int kp = 0; kp < 16; kp++) {
        // two float4 loads cover element kp of fibers 0..3
        float4 v01 = *reinterpret_cast<const float4*>(IN + pb + kp * PS);
        float4 v23 = *reinterpret_cast<const float4*>(IN + pb + 2 + kp * PS);
        ull xp[4];
        xp[0] = *reinterpret_cast<ull*>(&v01);
        xp[1] = *(reinterpret_cast<ull*>(&v01) + 1);
        xp[2] = *reinterpret_cast<ull*>(&v23);
        xp[3] = *(reinterpret_cast<ull*>(&v23) + 1);

        const float4* Gr = G + kp * 16 + q;
        ulonglong2 g0 = *reinterpret_cast<const ulonglong2*>(Gr + 0);
        ulonglong2 g1 = *reinterpret_cast<const ulonglong2*>(Gr + 4);
        ulonglong2 g2 = *reinterpret_cast<const ulonglong2*>(Gr + 8);
        ulonglong2 g3 = *reinterpret_cast<const ulonglong2*>(Gr + 12);
        #pragma unroll
        for (int f = 0; f < 4; f++) {
            accA[f][0] = ffma2(g0.x, xp[f], accA[f][0]);
            accB[f][0] = ffma2(g0.y, xp[f], accB[f][0]);
            accA[f][1] = ffma2(g1.x, xp[f], accA[f][1]);
            accB[f][1] = ffma2(g1.y, xp[f], accB[f][1]);
            accA[f][2] = ffma2(g2.x, xp[f], accA[f][2]);
            accB[f][2] = ffma2(g2.y, xp[f], accB[f][2]);
            accA[f][3] = ffma2(g3.x, xp[f], accA[f][3]);
            accB[f][3] = ffma2(g3.y, xp[f], accB[f][3]);
        }
    }
    // stores: fibers f,f+1 adjacent -> float4 store per (j, pair)
    #pragma unroll
    for (int j = 0; j < 4; j++) {
        int k = q + 4 * j;
        float a0, a1, b0, b1;
        unpack2(accA[0][j], a0, a1); unpack2(accB[0][j], b0, b1);
        float2 y0 = make_float2(a0 - b1, a1 + b0);
        unpack2(accA[1][j], a0, a1); unpack2(accB[1][j], b0, b1);
        float2 y1 = make_float2(a0 - b1, a1 + b0);
        *reinterpret_cast<float4*>(OUT + pb + k * PS) =
            make_float4(y0.x, y0.y, y1.x, y1.y);
        unpack2(accA[2][j], a0, a1); unpack2(accB[2][j], b0, b1);
        y0 = make_float2(a0 - b1, a1 + b0);
        unpack2(accA[3][j], a0, a1); unpack2(accB[3][j], b0, b1);
        y1 = make_float2(a0 - b1, a1 + b0);
        *reinterpret_cast<float4*>(OUT + pb + 2 + k * PS) =
            make_float4(y0.x, y0.y, y1.x, y1.y);
    }
}

__global__ __launch_bounds__(256)
void ulayer_kernel(const float* __restrict__ thetas,
                   const float* __restrict__ evecs,
                   const float* __restrict__ evals,
                   const float* __restrict__ sreal,
                   const float* __restrict__ simag,
                   float* __restrict__ out)
{
    extern __shared__ float2 smem[];
    float2* A  = smem;                  // BUF_F2 float2
    float2* Bv = smem + BUF_F2;         // BUF_F2 float2
    float4* g4 = reinterpret_cast<float4*>(smem + 2 * BUF_F2); // 3*256 float4

    const int t = threadIdx.x;
    const int b = blockIdx.x;

    // scratch overlay inside B (dead until step 0 writes B, after syncs)
    float* Vs = reinterpret_cast<float*>(Bv);   // 16 rows, stride 17
    float* cs = reinterpret_cast<float*>(Bv) + 288;
    float* sn = reinterpret_cast<float*>(Bv) + 336;

    // ---- stage V and sincos ----
    {
        int j = t >> 4, m = t & 15;
        Vs[j * 17 + m] = evecs[t];               // V[j][m]
    }
    if (t < 48) {
        int g = t >> 4, m = t & 15;
        float ang = thetas[g] * evals[m];
        float s, c;
        sincosf(ang, &s, &c);
        cs[g * 16 + m] = c;
        sn[g * 16 + m] = s;
    }
    __syncthreads();

    // ---- build gates, layout G[kp*16 + k] = (Ur, Ur, Ui, Ui) ----
    {
        int k = t >> 4, kp = t & 15;
        #pragma unroll
        for (int g = 0; g < 3; g++) {
            float ar = 0.f, ai = 0.f;
            #pragma unroll
            for (int m = 0; m < 16; m++) {
                float p = Vs[k * 17 + m] * Vs[kp * 17 + m];
                ar += p * cs[g * 16 + m];
                ai += p * sn[g * 16 + m];
            }
            // Ur = ar, Ui = -ai
            g4[g * 256 + kp * 16 + k] = make_float4(ar, ar, -ai, -ai);
        }
    }

    // ---- load state into A (concurrent with gate build) ----
    const float* srg = sreal + b * DIM;
    const float* sig = simag + b * DIM;
    #pragma unroll
    for (int w = 0; w < 16; w++) {
        int i = t + w * 256;
        A[phys(i)] = make_float2(srg[i], sig[i]);
    }
    __syncthreads();

    const int h = t >> 2, q = t & 3;   // h in [0,64), q in [0,4)

    // step 0: U2 on stride-1 index, fibers 4h..4h+3
    do_step0(A, Bv, g4 + 2 * 256, h, q);
    __syncthreads();

    // step 1: U1 on stride-16 index; fibers f0=4h..4h+3 (same a, c=f&15)
    {
        int f0 = 4 * h;
        int pb = (f0 >> 4) * 290 + (f0 & 15);
        do_step12<18>(Bv, A, g4 + 1 * 256, pb, q);
    }
    __syncthreads();

    // step 2: U0 on stride-256 index; fibers f0=4h..4h+3
    {
        int f0 = 4 * h;
        int pb = f0 + 2 * (f0 >> 4);
        do_step12<290>(A, Bv, g4 + 0 * 256, pb, q);
    }
    __syncthreads();

    // ---- write output [2, BATCH, DIM] from B ----
    float* outr = out + b * DIM;
    float* outi = out + (size_t)BATCH * DIM + b * DIM;
    #pragma unroll
    for (int w = 0; w < 16; w++) {
        int i = t + w * 256;
        float2 v = Bv[phys(i)];
        outr[i] = v.x;
        outi[i] = v.y;
    }
}

extern "C" void kernel_launch(void* const* d_in, const int* in_sizes, int n_in,
                              void* d_out, int out_size) {
    const float* thetas = (const float*)d_in[0];
    const float* evecs  = (const float*)d_in[1];
    const float* evals  = (const float*)d_in[2];
    const float* sreal  = (const float*)d_in[3];
    const float* simag  = (const float*)d_in[4];

    const int smem_bytes = 2 * BUF_F2 * sizeof(float2) + 3 * 256 * sizeof(float4);
    static bool attr_set = false;
    if (!attr_set) {
        cudaFuncSetAttribute(ulayer_kernel,
                             cudaFuncAttributeMaxDynamicSharedMemorySize,
                             smem_bytes);
        attr_set = true;
    }
    ulayer_kernel<<<BATCH, 256, smem_bytes>>>(thetas, evecs, evals,
                                              sreal, simag, (float*)d_out);
}

// round 6
// speedup vs baseline: 1.6650x; 1.0175x over previous
#include <cuda_runtime.h>

#define BATCH 128
#define DIM   4096

typedef unsigned long long ull;

__device__ __forceinline__ void unpack2(ull v, float& lo, float& hi) {
    asm("mov.b64 {%0, %1}, %2;" : "=f"(lo), "=f"(hi) : "l"(v));
}
__device__ __forceinline__ ull ffma2(ull a, ull b, ull c) {
    ull d;
    asm("fma.rn.f32x2 %0, %1, %2, %3;" : "=l"(d) : "l"(a), "l"(b), "l"(c));
    return d;
}

// padded smem layout: float4-aligned, spreads strided fibers across banks
__device__ __forceinline__ int phys(int i) {
    return i + 2 * (i >> 4) + 2 * (i >> 8);
}
#define BUF_F2 4640

// Complex accumulation without operand swap:
//   accA += (Ur,Ur)*(xr,xi) ; accB += (Ui,Ui)*(xr,xi)
//   yr = accA.lo - accB.hi ; yi = accA.hi + accB.lo
// Gate entry float4(Ur,Ur,Ui,Ui), read as ulonglong2 {gA, gB}.

struct GateRegs { ulonglong2 g0, g1, g2, g3; };

__device__ __forceinline__ GateRegs load_gates(const float4* __restrict__ Gr) {
    GateRegs g;
    g.g0 = *reinterpret_cast<const ulonglong2*>(Gr + 0);
    g.g1 = *reinterpret_cast<const ulonglong2*>(Gr + 4);
    g.g2 = *reinterpret_cast<const ulonglong2*>(Gr + 8);
    g.g3 = *reinterpret_cast<const ulonglong2*>(Gr + 12);
    return g;
}

__device__ __forceinline__ void mac_all(const GateRegs& g, const ull xp[4],
                                        ull accA[4][4], ull accB[4][4]) {
    #pragma unroll
    for (int f = 0; f < 4; f++) {
        accA[f][0] = ffma2(g.g0.x, xp[f], accA[f][0]);
        accB[f][0] = ffma2(g.g0.y, xp[f], accB[f][0]);
        accA[f][1] = ffma2(g.g1.x, xp[f], accA[f][1]);
        accB[f][1] = ffma2(g.g1.y, xp[f], accB[f][1]);
        accA[f][2] = ffma2(g.g2.x, xp[f], accA[f][2]);
        accB[f][2] = ffma2(g.g2.y, xp[f], accB[f][2]);
        accA[f][3] = ffma2(g.g3.x, xp[f], accA[f][3]);
        accB[f][3] = ffma2(g.g3.y, xp[f], accB[f][3]);
    }
}

// ---- step 0: contracted index has logical stride 1 ----
// Thread (h, q): fibers 4h..4h+3 (fiber phys stride 18), outputs k = q+4j.
// Software-pipelined over kp pairs (one float4 per fiber covers kp, kp+1).
__device__ __forceinline__ void do_step0(const float2* __restrict__ IN,
                                         float2* __restrict__ OUT,
                                         const float4* __restrict__ G,
                                         int h, int q)
{
    const int pb0 = 72 * h + 2 * (h >> 2);

    ull accA[4][4], accB[4][4];
    #pragma unroll
    for (int f = 0; f < 4; f++)
        #pragma unroll
        for (int j = 0; j < 4; j++) { accA[f][j] = 0ULL; accB[f][j] = 0ULL; }

    // prefetch kp2 = 0
    float4 xv[4];
    #pragma unroll
    for (int f = 0; f < 4; f++)
        xv[f] = *reinterpret_cast<const float4*>(IN + pb0 + 18 * f);
    GateRegs ga = load_gates(G + 0 * 16 + q);
    GateRegs gb = load_gates(G + 1 * 16 + q);

    #pragma unroll
    for (int kp2 = 0; kp2 < 8; kp2++) {
        // stage current x into packed regs
        ull xlo[4], xhi[4];
        #pragma unroll
        for (int f = 0; f < 4; f++) {
            xlo[f] = *reinterpret_cast<ull*>(&xv[f]);
            xhi[f] = *(reinterpret_cast<ull*>(&xv[f]) + 1);
        }
        // prefetch next iteration's x and gates
        GateRegs gan, gbn;
        if (kp2 < 7) {
            #pragma unroll
            for (int f = 0; f < 4; f++)
                xv[f] = *reinterpret_cast<const float4*>(
                    IN + pb0 + 18 * f + 2 * (kp2 + 1));
            gan = load_gates(G + (2 * kp2 + 2) * 16 + q);
            gbn = load_gates(G + (2 * kp2 + 3) * 16 + q);
        }
        mac_all(ga, xlo, accA, accB);
        mac_all(gb, xhi, accA, accB);
        if (kp2 < 7) { ga = gan; gb = gbn; }
    }
    #pragma unroll
    for (int f = 0; f < 4; f++)
        #pragma unroll
        for (int j = 0; j < 4; j++) {
            float alo, ahi, blo, bhi;
            unpack2(accA[f][j], alo, ahi);
            unpack2(accB[f][j], blo, bhi);
            OUT[pb0 + 18 * f + (q + 4 * j)] = make_float2(alo - bhi, ahi + blo);
        }
}

// ---- steps 1 & 2: 4 fibers adjacent in phys (+1); PS = phys stride along kp
template<int PS>
__device__ __forceinline__ void do_step12(const float2* __restrict__ IN,
                                          float2* __restrict__ OUT,
                                          const float4* __restrict__ G,
                                          int pb, int q)
{
    ull accA[4][4], accB[4][4];
    #pragma unroll
    for (int f = 0; f < 4; f++)
        #pragma unroll
        for (int j = 0; j < 4; j++) { accA[f][j] = 0ULL; accB[f][j] = 0ULL; }

    // prefetch kp = 0
    float4 v01 = *reinterpret_cast<const float4*>(IN + pb);
    float4 v23 = *reinterpret_cast<const float4*>(IN + pb + 2);
    GateRegs g = load_gates(G + q);

    #pragma unroll
    for (int kp = 0; kp < 16; kp++) {
        ull xp[4];
        xp[0] = *reinterpret_cast<ull*>(&v01);
        xp[1] = *(reinterpret_cast<ull*>(&v01) + 1);
        xp[2] = *reinterpret_cast<ull*>(&v23);
        xp[3] = *(reinterpret_cast<ull*>(&v23) + 1);

        GateRegs gn;
        if (kp < 15) {
            v01 = *reinterpret_cast<const float4*>(IN + pb + (kp + 1) * PS);
            v23 = *reinterpret_cast<const float4*>(IN + pb + 2 + (kp + 1) * PS);
            gn = load_gates(G + (kp + 1) * 16 + q);
        }
        mac_all(g, xp, accA, accB);
        if (kp < 15) g = gn;
    }
    #pragma unroll
    for (int j = 0; j < 4; j++) {
        int k = q + 4 * j;
        float a0, a1, b0, b1;
        unpack2(accA[0][j], a0, a1); unpack2(accB[0][j], b0, b1);
        float2 y0 = make_float2(a0 - b1, a1 + b0);
        unpack2(accA[1][j], a0, a1); unpack2(accB[1][j], b0, b1);
        float2 y1 = make_float2(a0 - b1, a1 + b0);
        *reinterpret_cast<float4*>(OUT + pb + k * PS) =
            make_float4(y0.x, y0.y, y1.x, y1.y);
        unpack2(accA[2][j], a0, a1); unpack2(accB[2][j], b0, b1);
        y0 = make_float2(a0 - b1, a1 + b0);
        unpack2(accA[3][j], a0, a1); unpack2(accB[3][j], b0, b1);
        y1 = make_float2(a0 - b1, a1 + b0);
        *reinterpret_cast<float4*>(OUT + pb + 2 + k * PS) =
            make_float4(y0.x, y0.y, y1.x, y1.y);
    }
}

__global__ __launch_bounds__(256, 1)
void ulayer_kernel(const float* __restrict__ thetas,
                   const float* __restrict__ evecs,
                   const float* __restrict__ evals,
                   const float* __restrict__ sreal,
                   const float* __restrict__ simag,
                   float* __restrict__ out)
{
    extern __shared__ float2 smem[];
    float2* A  = smem;                  // BUF_F2 float2
    float2* Bv = smem + BUF_F2;         // BUF_F2 float2
    float4* g4 = reinterpret_cast<float4*>(smem + 2 * BUF_F2); // 3*256 float4

    const int t = threadIdx.x;
    const int b = blockIdx.x;

    // scratch overlay inside B (dead until step 0 writes B, after syncs)
    float* Vs = reinterpret_cast<float*>(Bv);   // 16 rows, stride 17
    float* cs = reinterpret_cast<float*>(Bv) + 288;
    float* sn = reinterpret_cast<float*>(Bv) + 336;

    // ---- stage V and sincos ----
    {
        int j = t >> 4, m = t & 15;
        Vs[j * 17 + m] = evecs[t];               // V[j][m]
    }
    if (t < 48) {
        int g = t >> 4, m = t & 15;
        float ang = thetas[g] * evals[m];
        float s, c;
        sincosf(ang, &s, &c);
        cs[g * 16 + m] = c;
        sn[g * 16 + m] = s;
    }
    __syncthreads();

    // ---- build gates, layout G[kp*16 + k] = (Ur, Ur, Ui, Ui) ----
    {
        int k = t >> 4, kp = t & 15;
        #pragma unroll
        for (int g = 0; g < 3; g++) {
            float ar = 0.f, ai = 0.f;
            #pragma unroll
            for (int m = 0; m < 16; m++) {
                float p = Vs[k * 17 + m] * Vs[kp * 17 + m];
                ar += p * cs[g * 16 + m];
                ai += p * sn[g * 16 + m];
            }
            // Ur = ar, Ui = -ai
            g4[g * 256 + kp * 16 + k] = make_float4(ar, ar, -ai, -ai);
        }
    }

    // ---- load state into A (concurrent with gate build) ----
    const float* srg = sreal + b * DIM;
    const float* sig = simag + b * DIM;
    #pragma unroll
    for (int w = 0; w < 16; w++) {
        int i = t + w * 256;
        A[phys(i)] = make_float2(srg[i], sig[i]);
    }
    __syncthreads();

    const int h = t >> 2, q = t & 3;   // h in [0,64), q in [0,4)

    // step 0: U2 on stride-1 index, fibers 4h..4h+3
    do_step0(A, Bv, g4 + 2 * 256, h, q);
    __syncthreads();

    // step 1: U1 on stride-16 index; fibers f0=4h..4h+3
    {
        int f0 = 4 * h;
        int pb = (f0 >> 4) * 290 + (f0 & 15);
        do_step12<18>(Bv, A, g4 + 1 * 256, pb, q);
    }
    __syncthreads();

    // step 2: U0 on stride-256 index; fibers f0=4h..4h+3
    {
        int f0 = 4 * h;
        int pb = f0 + 2 * (f0 >> 4);
        do_step12<290>(A, Bv, g4 + 0 * 256, pb, q);
    }
    __syncthreads();

    // ---- write output [2, BATCH, DIM] from B ----
    float* outr = out + b * DIM;
    float* outi = out + (size_t)BATCH * DIM + b * DIM;
    #pragma unroll
    for (int w = 0; w < 16; w++) {
        int i = t + w * 256;
        float2 v = Bv[phys(i)];
        outr[i] = v.x;
        outi[i] = v.y;
    }
}

extern "C" void kernel_launch(void* const* d_in, const int* in_sizes, int n_in,
                              void* d_out, int out_size) {
    const float* thetas = (const float*)d_in[0];
    const float* evecs  = (const float*)d_in[1];
    const float* evals  = (const float*)d_in[2];
    const float* sreal  = (const float*)d_in[3];
    const float* simag  = (const float*)d_in[4];

    const int smem_bytes = 2 * BUF_F2 * sizeof(float2) + 3 * 256 * sizeof(float4);
    static bool attr_set = false;
    if (!attr_set) {
        cudaFuncSetAttribute(ulayer_kernel,
                             cudaFuncAttributeMaxDynamicSharedMemorySize,
                             smem_bytes);
        attr_set = true;
    }
    ulayer_kernel<<<BATCH, 256, smem_bytes>>>(thetas, evecs, evals,
                                              sreal, simag, (float*)d_out);
}